// round 7
// baseline (speedup 1.0000x reference)
#include <cuda_runtime.h>
#include <cuda_bf16.h>

// Problem constants
#define SDIM     785          // seq incl. CLS
#define SLABSZ   616225       // 785*785
#define NP       784
#define NL       12
#define NB       4
#define NH       12
#define NSLAB    (NL*NB*NH)   // 576
#define KTH      588
#define LN_EPS   1e-5f
#define CHUNKS   4
#define GPC      49           // groups per chunk

// Scratch accumulator: g_sums[b][c] for column j = c+1.
// Zero-initialized at module load; finalize_kernel re-zeroes it after use,
// so every launch / graph replay starts from 0.
__device__ float g_sums[NB * NP];

// ---------------------------------------------------------------------------
// Kernel 1: vectorized column-sum + chunk-3 locally-summed edge correction.
// (unchanged from the 221.9us round-3 version)
// ---------------------------------------------------------------------------
__global__ __launch_bounds__(224) void colsum_vec(const float* __restrict__ att) {
    const int blk   = blockIdx.x;           // 0 .. NSLAB*CHUNKS-1
    const int chunk = blk & (CHUNKS - 1);
    const int m     = blk >> 2;             // slab 0..575
    const int t     = threadIdx.x;

    const int b       = (m / NH) & 3;       // m = l*48 + b*12 + h
    const int r_first = (4 - (m & 3)) & 3;  // first row with float-shift 0
    const int Gm      = (785 - r_first) >> 2;
    const int g0      = chunk * GPC;
    int gcnt = Gm - g0;
    if (gcnt > GPC) gcnt = GPC;
    float* gs = &g_sums[b * NP];

    if (t <= 196 && gcnt > 0) {
        const float* fp = att + (size_t)m * SLABSZ
                              + (size_t)(r_first + 4 * g0) * SDIM;   // 16B-aligned

        float a0 = 0.f, a1 = 0.f, a2 = 0.f, a3 = 0.f, a4 = 0.f, a5 = 0.f, a6 = 0.f;

        #pragma unroll 2
        for (int g = 0; g < gcnt; ++g) {
            const float4 x = __ldcs((const float4*)(fp)        + t);  // shift 0
            const float4 y = __ldcs((const float4*)(fp +  784) + t);  // shift 1
            const float4 z = __ldcs((const float4*)(fp + 1568) + t);  // shift 2
            const float4 w = __ldcs((const float4*)(fp + 2352) + t);  // shift 3

            a3 += x.x; a4 += x.y; a5 += x.z; a6 += x.w;   // cols 4t .. 4t+3
            a2 += y.x; a3 += y.y; a4 += y.z; a5 += y.w;   // cols 4t-1 .. 4t+2
            a1 += z.x; a2 += z.y; a3 += z.z; a4 += z.w;   // cols 4t-2 .. 4t+1
            a0 += w.x; a1 += w.y; a2 += w.z; a3 += w.w;   // cols 4t-3 .. 4t
            fp += 4 * SDIM;
        }

        const float acc[7] = {a0, a1, a2, a3, a4, a5, a6};
        const int cbase = 4 * t - 3;
        #pragma unroll
        for (int d = 0; d < 7; ++d) {
            const int c = cbase + d;              // column j in [1,784]
            if (c >= 1 && c <= NP) atomicAdd(&gs[c - 1], acc[d]);
        }
    }

    // Edge-row correction (chunk-3 block only, locally summed -> 1 atomic/col):
    //   m%4==0: cover 0..783  -> -row0, +row784
    //   m%4==1: cover 3..782  -> +rows 1,2,783,784
    //   m%4==2: cover 2..781  -> +rows 1,782,783,784
    //   m%4==3: cover 1..784  -> nothing
    if (chunk == CHUNKS - 1) {
        const int mm = m & 3;
        if (mm != 3) {
            const float* base = att + (size_t)m * SLABSZ;
            int   rows[4]; float sgn[4]; int n;
            if (mm == 0)      { rows[0]=0; sgn[0]=-1.f; rows[1]=784; sgn[1]=1.f; n=2; }
            else if (mm == 1) { rows[0]=1; rows[1]=2;   rows[2]=783; rows[3]=784;
                                sgn[0]=sgn[1]=sgn[2]=sgn[3]=1.f; n=4; }
            else              { rows[0]=1; rows[1]=782; rows[2]=783; rows[3]=784;
                                sgn[0]=sgn[1]=sgn[2]=sgn[3]=1.f; n=4; }
            for (int c = t; c < NP; c += blockDim.x) {
                float s = 0.f;
                for (int i = 0; i < n; ++i)
                    s += sgn[i] * __ldg(base + (size_t)rows[i] * SDIM + (c + 1));
                atomicAdd(&gs[c], s);
            }
        }
    }
}

// ---------------------------------------------------------------------------
// Kernel 2: LayerNorm + sigmoid + radix-select kth-smallest + mask.
// Single fused (sum, sumsq) reduction; resets g_sums for the next replay.
// ---------------------------------------------------------------------------
__global__ __launch_bounds__(1024) void finalize_kernel(const float* __restrict__ gamma,
                                                        const float* __restrict__ beta,
                                                        float* __restrict__ out) {
    __shared__ float red_s[32];
    __shared__ float red_q[32];
    __shared__ int   hist[256];
    __shared__ unsigned s_prefix;
    __shared__ int      s_k;

    const int b = blockIdx.x;
    const int t = threadIdx.x;
    const int wid = t >> 5, lid = t & 31;
    const bool active = (t < NP);

    float s = 0.0f;
    if (active) {
        s = g_sums[b * NP + t] * (1.0f / 144.0f);
        g_sums[b * NP + t] = 0.0f;          // reset for next graph replay
    }
    if (t == 0) { s_prefix = 0u; s_k = KTH; }

    // Fused (sum, sumsq) block reduction
    float vs = s, vq = s * s;
    #pragma unroll
    for (int o = 16; o > 0; o >>= 1) {
        vs += __shfl_xor_sync(0xFFFFFFFFu, vs, o);
        vq += __shfl_xor_sync(0xFFFFFFFFu, vq, o);
    }
    if (lid == 0) { red_s[wid] = vs; red_q[wid] = vq; }
    __syncthreads();
    if (wid == 0) {
        vs = red_s[lid]; vq = red_q[lid];
        #pragma unroll
        for (int o = 16; o > 0; o >>= 1) {
            vs += __shfl_xor_sync(0xFFFFFFFFu, vs, o);
            vq += __shfl_xor_sync(0xFFFFFFFFu, vq, o);
        }
        if (lid == 0) { red_s[0] = vs; red_q[0] = vq; }
    }
    __syncthreads();
    const float mu  = red_s[0] * (1.0f / (float)NP);
    const float ex2 = red_q[0] * (1.0f / (float)NP);
    const float var = fmaxf(ex2 - mu * mu, 0.0f);
    const float rstd = rsqrtf(var + LN_EPS);

    float p = 0.0f;
    unsigned key = 0u;
    if (active) {
        const float ln = (s - mu) * rstd * gamma[t] + beta[t];
        p   = 1.0f / (1.0f + expf(-ln));
        key = __float_as_uint(p);           // monotone: p > 0
    }

    #pragma unroll
    for (int pass = 0; pass < 4; ++pass) {
        const int shift = 24 - 8 * pass;
        const unsigned hi_mask = (pass == 0) ? 0u : (0xFFFFFFFFu << (shift + 8));

        __syncthreads();                    // protect hist/prefix from prev pass
        if (t < 256) hist[t] = 0;
        __syncthreads();

        const unsigned prefix = s_prefix;
        const int k = s_k;
        if (active && ((key & hi_mask) == prefix))
            atomicAdd(&hist[(key >> shift) & 255], 1);
        __syncthreads();

        if (wid == 0) {
            int sub = 0;
            #pragma unroll
            for (int i = 0; i < 8; ++i) sub += hist[lid * 8 + i];
            int inc = sub;
            #pragma unroll
            for (int o = 1; o < 32; o <<= 1) {
                int v = __shfl_up_sync(0xFFFFFFFFu, inc, o);
                if (lid >= o) inc += v;
            }
            const int ex = inc - sub;
            if (ex < k && k <= inc) {           // exactly one lane
                int cum = ex;
                #pragma unroll
                for (int i = 0; i < 8; ++i) {
                    const int h = hist[lid * 8 + i];
                    if (k <= cum + h) {
                        s_prefix = prefix | ((unsigned)(lid * 8 + i) << shift);
                        s_k = k - cum;
                        break;
                    }
                    cum += h;
                }
            }
        }
    }
    __syncthreads();

    const float thr = __uint_as_float(s_prefix);   // exact kth-smallest p
    if (active) out[b * NP + t] = (p > thr) ? 1.0f : 0.0f;
}

// ---------------------------------------------------------------------------
// Launch contract
// ---------------------------------------------------------------------------
extern "C" void kernel_launch(void* const* d_in, const int* in_sizes, int n_in,
                              void* d_out, int out_size) {
    const float* att   = (const float*)d_in[0];   // [12,4,12,785,785] f32
    const float* gamma = (const float*)d_in[1];   // [784] f32
    const float* beta  = (const float*)d_in[2];   // [784] f32
    float* out = (float*)d_out;                   // [4,784] f32

    colsum_vec<<<NSLAB * CHUNKS, 224>>>(att);
    finalize_kernel<<<NB, 1024>>>(gamma, beta, out);
}

// round 9
// speedup vs baseline: 1.0276x; 1.0276x over previous
#include <cuda_runtime.h>
#include <cuda_bf16.h>

// Problem constants
#define SDIM     785          // seq incl. CLS
#define SLABSZ   616225       // 785*785
#define NP       784
#define NL       12
#define NB       4
#define NH       12
#define NSLAB    (NL*NB*NH)   // 576
#define KTH      588
#define LN_EPS   1e-5f
#define CHUNKS   4
#define GPC      49           // groups per chunk

// Scratch accumulator: g_sums[b][c] for column j = c+1.
// Zero-initialized at module load; finalize_kernel re-zeroes it after use,
// so every launch / graph replay starts from 0.
__device__ float g_sums[NB * NP];

// ---------------------------------------------------------------------------
// Kernel 1: vectorized column-sum + chunk-3 locally-summed edge correction.
// Main loop identical to the proven round-3 version. Ends with a PDL trigger
// so the finalize grid can launch under this kernel's tail.
// ---------------------------------------------------------------------------
__global__ __launch_bounds__(224) void colsum_vec(const float* __restrict__ att) {
    const int blk   = blockIdx.x;           // 0 .. NSLAB*CHUNKS-1
    const int chunk = blk & (CHUNKS - 1);
    const int m     = blk >> 2;             // slab 0..575
    const int t     = threadIdx.x;

    const int b       = (m / NH) & 3;       // m = l*48 + b*12 + h
    const int r_first = (4 - (m & 3)) & 3;  // first row with float-shift 0
    const int Gm      = (785 - r_first) >> 2;
    const int g0      = chunk * GPC;
    int gcnt = Gm - g0;
    if (gcnt > GPC) gcnt = GPC;
    float* gs = &g_sums[b * NP];

    if (t <= 196 && gcnt > 0) {
        const float* fp = att + (size_t)m * SLABSZ
                              + (size_t)(r_first + 4 * g0) * SDIM;   // 16B-aligned

        float a0 = 0.f, a1 = 0.f, a2 = 0.f, a3 = 0.f, a4 = 0.f, a5 = 0.f, a6 = 0.f;

        #pragma unroll 2
        for (int g = 0; g < gcnt; ++g) {
            const float4 x = __ldcs((const float4*)(fp)        + t);  // shift 0
            const float4 y = __ldcs((const float4*)(fp +  784) + t);  // shift 1
            const float4 z = __ldcs((const float4*)(fp + 1568) + t);  // shift 2
            const float4 w = __ldcs((const float4*)(fp + 2352) + t);  // shift 3

            a3 += x.x; a4 += x.y; a5 += x.z; a6 += x.w;   // cols 4t .. 4t+3
            a2 += y.x; a3 += y.y; a4 += y.z; a5 += y.w;   // cols 4t-1 .. 4t+2
            a1 += z.x; a2 += z.y; a3 += z.z; a4 += z.w;   // cols 4t-2 .. 4t+1
            a0 += w.x; a1 += w.y; a2 += w.z; a3 += w.w;   // cols 4t-3 .. 4t
            fp += 4 * SDIM;
        }

        const float acc[7] = {a0, a1, a2, a3, a4, a5, a6};
        const int cbase = 4 * t - 3;
        #pragma unroll
        for (int d = 0; d < 7; ++d) {
            const int c = cbase + d;              // column j in [1,784]
            if (c >= 1 && c <= NP) atomicAdd(&gs[c - 1], acc[d]);
        }
    }

    // Edge-row correction (chunk-3 block only, locally summed -> 1 atomic/col):
    //   m%4==0: cover 0..783  -> -row0, +row784
    //   m%4==1: cover 3..782  -> +rows 1,2,783,784
    //   m%4==2: cover 2..781  -> +rows 1,782,783,784
    //   m%4==3: cover 1..784  -> nothing
    if (chunk == CHUNKS - 1) {
        const int mm = m & 3;
        if (mm != 3) {
            const float* base = att + (size_t)m * SLABSZ;
            int   rows[4]; float sgn[4]; int n;
            if (mm == 0)      { rows[0]=0; sgn[0]=-1.f; rows[1]=784; sgn[1]=1.f; n=2; }
            else if (mm == 1) { rows[0]=1; rows[1]=2;   rows[2]=783; rows[3]=784;
                                sgn[0]=sgn[1]=sgn[2]=sgn[3]=1.f; n=4; }
            else              { rows[0]=1; rows[1]=782; rows[2]=783; rows[3]=784;
                                sgn[0]=sgn[1]=sgn[2]=sgn[3]=1.f; n=4; }
            for (int c = t; c < NP; c += blockDim.x) {
                float s = 0.f;
                for (int i = 0; i < n; ++i)
                    s += sgn[i] * __ldg(base + (size_t)rows[i] * SDIM + (c + 1));
                atomicAdd(&gs[c], s);
            }
        }
    }

    // PDL trigger: all prior writes (incl. L2 atomics) become visible to the
    // dependent grid's griddepcontrol.wait. All threads reach this point.
    asm volatile("griddepcontrol.launch_dependents;" ::: "memory");
}

// ---------------------------------------------------------------------------
// Kernel 2 (PDL secondary): prefetch params, wait for primary, then
// LayerNorm + sigmoid + radix-select kth-smallest + mask; resets g_sums.
// ---------------------------------------------------------------------------
__global__ __launch_bounds__(1024) void finalize_kernel(const float* __restrict__ gamma,
                                                        const float* __restrict__ beta,
                                                        float* __restrict__ out) {
    __shared__ float red_s[32];
    __shared__ float red_q[32];
    __shared__ int   hist[256];
    __shared__ unsigned s_prefix;
    __shared__ int      s_k;

    const int b = blockIdx.x;
    const int t = threadIdx.x;
    const int wid = t >> 5, lid = t & 31;
    const bool active = (t < NP);

    // ---- pre-wait work (overlaps with colsum tail) ----
    float gm = 0.f, bt = 0.f;
    if (active) { gm = __ldg(&gamma[t]); bt = __ldg(&beta[t]); }
    if (t == 0) { s_prefix = 0u; s_k = KTH; }

    // ---- wait for primary grid's writes to be visible ----
    asm volatile("griddepcontrol.wait;" ::: "memory");

    float s = 0.0f;
    if (active) {
        s = __ldcg(&g_sums[b * NP + t]) * (1.0f / 144.0f);
        g_sums[b * NP + t] = 0.0f;          // reset for next graph replay
    }

    // Fused (sum, sumsq) block reduction
    float vs = s, vq = s * s;
    #pragma unroll
    for (int o = 16; o > 0; o >>= 1) {
        vs += __shfl_xor_sync(0xFFFFFFFFu, vs, o);
        vq += __shfl_xor_sync(0xFFFFFFFFu, vq, o);
    }
    if (lid == 0) { red_s[wid] = vs; red_q[wid] = vq; }
    __syncthreads();
    if (wid == 0) {
        vs = red_s[lid]; vq = red_q[lid];
        #pragma unroll
        for (int o = 16; o > 0; o >>= 1) {
            vs += __shfl_xor_sync(0xFFFFFFFFu, vs, o);
            vq += __shfl_xor_sync(0xFFFFFFFFu, vq, o);
        }
        if (lid == 0) { red_s[0] = vs; red_q[0] = vq; }
    }
    __syncthreads();
    const float mu  = red_s[0] * (1.0f / (float)NP);
    const float ex2 = red_q[0] * (1.0f / (float)NP);
    const float var = fmaxf(ex2 - mu * mu, 0.0f);
    const float rstd = rsqrtf(var + LN_EPS);

    float p = 0.0f;
    unsigned key = 0u;
    if (active) {
        const float ln = (s - mu) * rstd * gm + bt;
        p   = 1.0f / (1.0f + expf(-ln));
        key = __float_as_uint(p);           // monotone: p > 0
    }

    #pragma unroll
    for (int pass = 0; pass < 4; ++pass) {
        const int shift = 24 - 8 * pass;
        const unsigned hi_mask = (pass == 0) ? 0u : (0xFFFFFFFFu << (shift + 8));

        __syncthreads();                    // protect hist/prefix from prev pass
        if (t < 256) hist[t] = 0;
        __syncthreads();

        const unsigned prefix = s_prefix;
        const int k = s_k;
        if (active && ((key & hi_mask) == prefix))
            atomicAdd(&hist[(key >> shift) & 255], 1);
        __syncthreads();

        if (wid == 0) {
            int sub = 0;
            #pragma unroll
            for (int i = 0; i < 8; ++i) sub += hist[lid * 8 + i];
            int inc = sub;
            #pragma unroll
            for (int o = 1; o < 32; o <<= 1) {
                int v = __shfl_up_sync(0xFFFFFFFFu, inc, o);
                if (lid >= o) inc += v;
            }
            const int ex = inc - sub;
            if (ex < k && k <= inc) {           // exactly one lane
                int cum = ex;
                #pragma unroll
                for (int i = 0; i < 8; ++i) {
                    const int h = hist[lid * 8 + i];
                    if (k <= cum + h) {
                        s_prefix = prefix | ((unsigned)(lid * 8 + i) << shift);
                        s_k = k - cum;
                        break;
                    }
                    cum += h;
                }
            }
        }
    }
    __syncthreads();

    const float thr = __uint_as_float(s_prefix);   // exact kth-smallest p
    if (active) out[b * NP + t] = (p > thr) ? 1.0f : 0.0f;
}

// ---------------------------------------------------------------------------
// Launch contract: colsum, then finalize as a PDL (programmatic stream
// serialization) secondary so its ramp overlaps colsum's tail.
// ---------------------------------------------------------------------------
extern "C" void kernel_launch(void* const* d_in, const int* in_sizes, int n_in,
                              void* d_out, int out_size) {
    const float* att   = (const float*)d_in[0];   // [12,4,12,785,785] f32
    const float* gamma = (const float*)d_in[1];   // [784] f32
    const float* beta  = (const float*)d_in[2];   // [784] f32
    float* out = (float*)d_out;                   // [4,784] f32

    colsum_vec<<<NSLAB * CHUNKS, 224>>>(att);

    cudaLaunchConfig_t cfg = {};
    cfg.gridDim  = dim3(NB);
    cfg.blockDim = dim3(1024);
    cfg.dynamicSmemBytes = 0;
    cfg.stream = 0;                               // legacy default stream
    cudaLaunchAttribute attr[1];
    attr[0].id = cudaLaunchAttributeProgrammaticStreamSerialization;
    attr[0].val.programmaticStreamSerializationAllowed = 1;
    cfg.attrs = attr;
    cfg.numAttrs = 1;
    cudaLaunchKernelEx(&cfg, finalize_kernel, gamma, beta, out);
}

// round 10
// speedup vs baseline: 1.0904x; 1.0611x over previous
#include <cuda_runtime.h>
#include <cuda_bf16.h>

// Problem constants
#define SDIM     785          // seq incl. CLS
#define SLABSZ   616225       // 785*785
#define NP       784
#define NL       12
#define NB       4
#define NH       12
#define NSLAB    (NL*NB*NH)   // 576
#define KTH      588
#define LN_EPS   1e-5f
#define CHUNKS   4
#define GPC      49           // groups per chunk
#define NTHR     224

// Scratch accumulator: g_sums[b][c] for column j = c+1.
// Zero-initialized at module load; finalize_kernel re-zeroes it after use,
// so every launch / graph replay starts from 0.
__device__ float g_sums[NB * NP];

// ---------------------------------------------------------------------------
// Kernel 1: vectorized column-sum, smem-staged atomics, PDL trigger at end.
// Main memory loop identical to the proven version: 4-row groups starting at
// rows with (m + r) % 4 == 0 give statically-known float shifts {0,1,2,3};
// every load is an aligned LDG.128; thread t owns float4 slot t with a fixed
// 7-wide column window [4t-3, 4t+3].
// Per-block results are staged in shared memory, then flushed with exactly
// ONE global atomic per column (784/block) — halves chip-wide REDG traffic
// and shortens block retirement before the PDL trigger.
// ---------------------------------------------------------------------------
__global__ __launch_bounds__(NTHR) void colsum_vec(const float* __restrict__ att) {
    __shared__ float s_acc[NP];

    const int blk   = blockIdx.x;           // 0 .. NSLAB*CHUNKS-1
    const int chunk = blk & (CHUNKS - 1);
    const int m     = blk >> 2;             // slab 0..575
    const int t     = threadIdx.x;

    const int b       = (m / NH) & 3;       // m = l*48 + b*12 + h
    const int r_first = (4 - (m & 3)) & 3;  // first row with float-shift 0
    const int Gm      = (785 - r_first) >> 2;
    const int g0      = chunk * GPC;
    int gcnt = Gm - g0;
    if (gcnt > GPC) gcnt = GPC;

    #pragma unroll
    for (int i = t; i < NP; i += NTHR) s_acc[i] = 0.0f;
    __syncthreads();

    if (t <= 196 && gcnt > 0) {
        const float* fp = att + (size_t)m * SLABSZ
                              + (size_t)(r_first + 4 * g0) * SDIM;   // 16B-aligned

        float a0 = 0.f, a1 = 0.f, a2 = 0.f, a3 = 0.f, a4 = 0.f, a5 = 0.f, a6 = 0.f;

        #pragma unroll 2
        for (int g = 0; g < gcnt; ++g) {
            const float4 x = __ldcs((const float4*)(fp)        + t);  // shift 0
            const float4 y = __ldcs((const float4*)(fp +  784) + t);  // shift 1
            const float4 z = __ldcs((const float4*)(fp + 1568) + t);  // shift 2
            const float4 w = __ldcs((const float4*)(fp + 2352) + t);  // shift 3

            a3 += x.x; a4 += x.y; a5 += x.z; a6 += x.w;   // cols 4t .. 4t+3
            a2 += y.x; a3 += y.y; a4 += y.z; a5 += y.w;   // cols 4t-1 .. 4t+2
            a1 += z.x; a2 += z.y; a3 += z.z; a4 += z.w;   // cols 4t-2 .. 4t+1
            a0 += w.x; a1 += w.y; a2 += w.z; a3 += w.w;   // cols 4t-3 .. 4t
            fp += 4 * SDIM;
        }

        const float acc[7] = {a0, a1, a2, a3, a4, a5, a6};
        const int cbase = 4 * t - 3;
        #pragma unroll
        for (int d = 0; d < 7; ++d) {
            const int c = cbase + d;              // column j in [1,784]
            if (c >= 1 && c <= NP) atomicAdd(&s_acc[c - 1], acc[d]);   // smem
        }
    }

    // Edge-row correction (chunk-3 block only), staged into smem too:
    //   m%4==0: cover 0..783  -> -row0, +row784
    //   m%4==1: cover 3..782  -> +rows 1,2,783,784
    //   m%4==2: cover 2..781  -> +rows 1,782,783,784
    //   m%4==3: cover 1..784  -> nothing
    if (chunk == CHUNKS - 1) {
        const int mm = m & 3;
        if (mm != 3) {
            const float* base = att + (size_t)m * SLABSZ;
            int   rows[4]; float sgn[4]; int n;
            if (mm == 0)      { rows[0]=0; sgn[0]=-1.f; rows[1]=784; sgn[1]=1.f; n=2; }
            else if (mm == 1) { rows[0]=1; rows[1]=2;   rows[2]=783; rows[3]=784;
                                sgn[0]=sgn[1]=sgn[2]=sgn[3]=1.f; n=4; }
            else              { rows[0]=1; rows[1]=782; rows[2]=783; rows[3]=784;
                                sgn[0]=sgn[1]=sgn[2]=sgn[3]=1.f; n=4; }
            for (int c = t; c < NP; c += NTHR) {
                float s = 0.f;
                for (int i = 0; i < n; ++i)
                    s += sgn[i] * __ldg(base + (size_t)rows[i] * SDIM + (c + 1));
                atomicAdd(&s_acc[c], s);                               // smem
            }
        }
    }
    __syncthreads();

    // Flush: exactly one global atomic per column.
    float* gs = &g_sums[b * NP];
    #pragma unroll
    for (int i = t; i < NP; i += NTHR) atomicAdd(&gs[i], s_acc[i]);

    // PDL trigger: after this, all prior writes (incl. L2 atomics) are
    // visible to the dependent grid's griddepcontrol.wait.
    asm volatile("griddepcontrol.launch_dependents;" ::: "memory");
}

// ---------------------------------------------------------------------------
// Kernel 2 (PDL secondary): prefetch params, wait for primary, then
// LayerNorm + sigmoid + radix-select kth-smallest + mask; resets g_sums.
// ---------------------------------------------------------------------------
__global__ __launch_bounds__(1024) void finalize_kernel(const float* __restrict__ gamma,
                                                        const float* __restrict__ beta,
                                                        float* __restrict__ out) {
    __shared__ float red_s[32];
    __shared__ float red_q[32];
    __shared__ int   hist[256];
    __shared__ unsigned s_prefix;
    __shared__ int      s_k;

    const int b = blockIdx.x;
    const int t = threadIdx.x;
    const int wid = t >> 5, lid = t & 31;
    const bool active = (t < NP);

    // ---- pre-wait work (overlaps with colsum tail) ----
    float gm = 0.f, bt = 0.f;
    if (active) { gm = __ldg(&gamma[t]); bt = __ldg(&beta[t]); }
    if (t == 0) { s_prefix = 0u; s_k = KTH; }

    // ---- wait for primary grid's writes to be visible ----
    asm volatile("griddepcontrol.wait;" ::: "memory");

    float s = 0.0f;
    if (active) {
        s = __ldcg(&g_sums[b * NP + t]) * (1.0f / 144.0f);
        g_sums[b * NP + t] = 0.0f;          // reset for next graph replay
    }

    // Fused (sum, sumsq) block reduction
    float vs = s, vq = s * s;
    #pragma unroll
    for (int o = 16; o > 0; o >>= 1) {
        vs += __shfl_xor_sync(0xFFFFFFFFu, vs, o);
        vq += __shfl_xor_sync(0xFFFFFFFFu, vq, o);
    }
    if (lid == 0) { red_s[wid] = vs; red_q[wid] = vq; }
    __syncthreads();
    if (wid == 0) {
        vs = red_s[lid]; vq = red_q[lid];
        #pragma unroll
        for (int o = 16; o > 0; o >>= 1) {
            vs += __shfl_xor_sync(0xFFFFFFFFu, vs, o);
            vq += __shfl_xor_sync(0xFFFFFFFFu, vq, o);
        }
        if (lid == 0) { red_s[0] = vs; red_q[0] = vq; }
    }
    __syncthreads();
    const float mu  = red_s[0] * (1.0f / (float)NP);
    const float ex2 = red_q[0] * (1.0f / (float)NP);
    const float var = fmaxf(ex2 - mu * mu, 0.0f);
    const float rstd = rsqrtf(var + LN_EPS);

    float p = 0.0f;
    unsigned key = 0u;
    if (active) {
        const float ln = (s - mu) * rstd * gm + bt;
        p   = 1.0f / (1.0f + expf(-ln));
        key = __float_as_uint(p);           // monotone: p > 0
    }

    #pragma unroll
    for (int pass = 0; pass < 4; ++pass) {
        const int shift = 24 - 8 * pass;
        const unsigned hi_mask = (pass == 0) ? 0u : (0xFFFFFFFFu << (shift + 8));

        __syncthreads();                    // protect hist/prefix from prev pass
        if (t < 256) hist[t] = 0;
        __syncthreads();

        const unsigned prefix = s_prefix;
        const int k = s_k;
        if (active && ((key & hi_mask) == prefix))
            atomicAdd(&hist[(key >> shift) & 255], 1);
        __syncthreads();

        if (wid == 0) {
            int sub = 0;
            #pragma unroll
            for (int i = 0; i < 8; ++i) sub += hist[lid * 8 + i];
            int inc = sub;
            #pragma unroll
            for (int o = 1; o < 32; o <<= 1) {
                int v = __shfl_up_sync(0xFFFFFFFFu, inc, o);
                if (lid >= o) inc += v;
            }
            const int ex = inc - sub;
            if (ex < k && k <= inc) {           // exactly one lane
                int cum = ex;
                #pragma unroll
                for (int i = 0; i < 8; ++i) {
                    const int h = hist[lid * 8 + i];
                    if (k <= cum + h) {
                        s_prefix = prefix | ((unsigned)(lid * 8 + i) << shift);
                        s_k = k - cum;
                        break;
                    }
                    cum += h;
                }
            }
        }
    }
    __syncthreads();

    const float thr = __uint_as_float(s_prefix);   // exact kth-smallest p
    if (active) out[b * NP + t] = (p > thr) ? 1.0f : 0.0f;
}

// ---------------------------------------------------------------------------
// Launch contract: colsum, then finalize as a PDL secondary so its ramp
// overlaps colsum's tail.
// ---------------------------------------------------------------------------
extern "C" void kernel_launch(void* const* d_in, const int* in_sizes, int n_in,
                              void* d_out, int out_size) {
    const float* att   = (const float*)d_in[0];   // [12,4,12,785,785] f32
    const float* gamma = (const float*)d_in[1];   // [784] f32
    const float* beta  = (const float*)d_in[2];   // [784] f32
    float* out = (float*)d_out;                   // [4,784] f32

    colsum_vec<<<NSLAB * CHUNKS, NTHR>>>(att);

    cudaLaunchConfig_t cfg = {};
    cfg.gridDim  = dim3(NB);
    cfg.blockDim = dim3(1024);
    cfg.dynamicSmemBytes = 0;
    cfg.stream = 0;                               // legacy default stream
    cudaLaunchAttribute attr[1];
    attr[0].id = cudaLaunchAttributeProgrammaticStreamSerialization;
    attr[0].val.programmaticStreamSerializationAllowed = 1;
    cfg.attrs = attr;
    cfg.numAttrs = 1;
    cudaLaunchKernelEx(&cfg, finalize_kernel, gamma, beta, out);
}

// round 11
// speedup vs baseline: 1.1176x; 1.0250x over previous
#include <cuda_runtime.h>
#include <cuda_bf16.h>

// Problem constants
#define SDIM     785          // seq incl. CLS
#define SLABSZ   616225       // 785*785
#define NP       784
#define NL       12
#define NB       4
#define NH       12
#define NSLAB    (NL*NB*NH)   // 576
#define KTH      588
#define LN_EPS   1e-5f
#define CHUNKS   4
#define GPC      49           // groups per chunk
#define NTHR     224

// Scratch accumulator: g_sums[b][c] for column j = c+1.
// Zero-initialized at module load; finalize_kernel re-zeroes it after use,
// so every launch / graph replay starts from 0.
__device__ float g_sums[NB * NP];

// ---------------------------------------------------------------------------
// Kernel 1: vectorized column-sum, smem-staged atomics, PDL trigger at end.
// Main memory loop identical to the proven version: 4-row groups starting at
// rows with (m + r) % 4 == 0 give statically-known float shifts {0,1,2,3};
// every load is an aligned LDG.128; thread t owns float4 slot t with a fixed
// 7-wide column window [4t-3, 4t+3].
// Per-block results are staged in shared memory, then flushed with exactly
// ONE global atomic per column (784/block) — halves chip-wide REDG traffic
// and shortens block retirement before the PDL trigger.
// ---------------------------------------------------------------------------
__global__ __launch_bounds__(NTHR) void colsum_vec(const float* __restrict__ att) {
    __shared__ float s_acc[NP];

    const int blk   = blockIdx.x;           // 0 .. NSLAB*CHUNKS-1
    const int chunk = blk & (CHUNKS - 1);
    const int m     = blk >> 2;             // slab 0..575
    const int t     = threadIdx.x;

    const int b       = (m / NH) & 3;       // m = l*48 + b*12 + h
    const int r_first = (4 - (m & 3)) & 3;  // first row with float-shift 0
    const int Gm      = (785 - r_first) >> 2;
    const int g0      = chunk * GPC;
    int gcnt = Gm - g0;
    if (gcnt > GPC) gcnt = GPC;

    #pragma unroll
    for (int i = t; i < NP; i += NTHR) s_acc[i] = 0.0f;
    __syncthreads();

    if (t <= 196 && gcnt > 0) {
        const float* fp = att + (size_t)m * SLABSZ
                              + (size_t)(r_first + 4 * g0) * SDIM;   // 16B-aligned

        float a0 = 0.f, a1 = 0.f, a2 = 0.f, a3 = 0.f, a4 = 0.f, a5 = 0.f, a6 = 0.f;

        #pragma unroll 2
        for (int g = 0; g < gcnt; ++g) {
            const float4 x = __ldcs((const float4*)(fp)        + t);  // shift 0
            const float4 y = __ldcs((const float4*)(fp +  784) + t);  // shift 1
            const float4 z = __ldcs((const float4*)(fp + 1568) + t);  // shift 2
            const float4 w = __ldcs((const float4*)(fp + 2352) + t);  // shift 3

            a3 += x.x; a4 += x.y; a5 += x.z; a6 += x.w;   // cols 4t .. 4t+3
            a2 += y.x; a3 += y.y; a4 += y.z; a5 += y.w;   // cols 4t-1 .. 4t+2
            a1 += z.x; a2 += z.y; a3 += z.z; a4 += z.w;   // cols 4t-2 .. 4t+1
            a0 += w.x; a1 += w.y; a2 += w.z; a3 += w.w;   // cols 4t-3 .. 4t
            fp += 4 * SDIM;
        }

        const float acc[7] = {a0, a1, a2, a3, a4, a5, a6};
        const int cbase = 4 * t - 3;
        #pragma unroll
        for (int d = 0; d < 7; ++d) {
            const int c = cbase + d;              // column j in [1,784]
            if (c >= 1 && c <= NP) atomicAdd(&s_acc[c - 1], acc[d]);   // smem
        }
    }

    // Edge-row correction (chunk-3 block only), staged into smem too:
    //   m%4==0: cover 0..783  -> -row0, +row784
    //   m%4==1: cover 3..782  -> +rows 1,2,783,784
    //   m%4==2: cover 2..781  -> +rows 1,782,783,784
    //   m%4==3: cover 1..784  -> nothing
    if (chunk == CHUNKS - 1) {
        const int mm = m & 3;
        if (mm != 3) {
            const float* base = att + (size_t)m * SLABSZ;
            int   rows[4]; float sgn[4]; int n;
            if (mm == 0)      { rows[0]=0; sgn[0]=-1.f; rows[1]=784; sgn[1]=1.f; n=2; }
            else if (mm == 1) { rows[0]=1; rows[1]=2;   rows[2]=783; rows[3]=784;
                                sgn[0]=sgn[1]=sgn[2]=sgn[3]=1.f; n=4; }
            else              { rows[0]=1; rows[1]=782; rows[2]=783; rows[3]=784;
                                sgn[0]=sgn[1]=sgn[2]=sgn[3]=1.f; n=4; }
            for (int c = t; c < NP; c += NTHR) {
                float s = 0.f;
                for (int i = 0; i < n; ++i)
                    s += sgn[i] * __ldg(base + (size_t)rows[i] * SDIM + (c + 1));
                atomicAdd(&s_acc[c], s);                               // smem
            }
        }
    }
    __syncthreads();

    // Flush: exactly one global atomic per column.
    float* gs = &g_sums[b * NP];
    #pragma unroll
    for (int i = t; i < NP; i += NTHR) atomicAdd(&gs[i], s_acc[i]);

    // PDL trigger: after this, all prior writes (incl. L2 atomics) are
    // visible to the dependent grid's griddepcontrol.wait.
    asm volatile("griddepcontrol.launch_dependents;" ::: "memory");
}

// ---------------------------------------------------------------------------
// Kernel 2 (PDL secondary): prefetch params, wait for primary, then
// LayerNorm + sigmoid + radix-select kth-smallest + mask; resets g_sums.
// ---------------------------------------------------------------------------
__global__ __launch_bounds__(1024) void finalize_kernel(const float* __restrict__ gamma,
                                                        const float* __restrict__ beta,
                                                        float* __restrict__ out) {
    __shared__ float red_s[32];
    __shared__ float red_q[32];
    __shared__ int   hist[256];
    __shared__ unsigned s_prefix;
    __shared__ int      s_k;

    const int b = blockIdx.x;
    const int t = threadIdx.x;
    const int wid = t >> 5, lid = t & 31;
    const bool active = (t < NP);

    // ---- pre-wait work (overlaps with colsum tail) ----
    float gm = 0.f, bt = 0.f;
    if (active) { gm = __ldg(&gamma[t]); bt = __ldg(&beta[t]); }
    if (t == 0) { s_prefix = 0u; s_k = KTH; }

    // ---- wait for primary grid's writes to be visible ----
    asm volatile("griddepcontrol.wait;" ::: "memory");

    float s = 0.0f;
    if (active) {
        s = __ldcg(&g_sums[b * NP + t]) * (1.0f / 144.0f);
        g_sums[b * NP + t] = 0.0f;          // reset for next graph replay
    }

    // Fused (sum, sumsq) block reduction
    float vs = s, vq = s * s;
    #pragma unroll
    for (int o = 16; o > 0; o >>= 1) {
        vs += __shfl_xor_sync(0xFFFFFFFFu, vs, o);
        vq += __shfl_xor_sync(0xFFFFFFFFu, vq, o);
    }
    if (lid == 0) { red_s[wid] = vs; red_q[wid] = vq; }
    __syncthreads();
    if (wid == 0) {
        vs = red_s[lid]; vq = red_q[lid];
        #pragma unroll
        for (int o = 16; o > 0; o >>= 1) {
            vs += __shfl_xor_sync(0xFFFFFFFFu, vs, o);
            vq += __shfl_xor_sync(0xFFFFFFFFu, vq, o);
        }
        if (lid == 0) { red_s[0] = vs; red_q[0] = vq; }
    }
    __syncthreads();
    const float mu  = red_s[0] * (1.0f / (float)NP);
    const float ex2 = red_q[0] * (1.0f / (float)NP);
    const float var = fmaxf(ex2 - mu * mu, 0.0f);
    const float rstd = rsqrtf(var + LN_EPS);

    float p = 0.0f;
    unsigned key = 0u;
    if (active) {
        const float ln = (s - mu) * rstd * gm + bt;
        p   = 1.0f / (1.0f + expf(-ln));
        key = __float_as_uint(p);           // monotone: p > 0
    }

    #pragma unroll
    for (int pass = 0; pass < 4; ++pass) {
        const int shift = 24 - 8 * pass;
        const unsigned hi_mask = (pass == 0) ? 0u : (0xFFFFFFFFu << (shift + 8));

        __syncthreads();                    // protect hist/prefix from prev pass
        if (t < 256) hist[t] = 0;
        __syncthreads();

        const unsigned prefix = s_prefix;
        const int k = s_k;
        if (active && ((key & hi_mask) == prefix))
            atomicAdd(&hist[(key >> shift) & 255], 1);
        __syncthreads();

        if (wid == 0) {
            int sub = 0;
            #pragma unroll
            for (int i = 0; i < 8; ++i) sub += hist[lid * 8 + i];
            int inc = sub;
            #pragma unroll
            for (int o = 1; o < 32; o <<= 1) {
                int v = __shfl_up_sync(0xFFFFFFFFu, inc, o);
                if (lid >= o) inc += v;
            }
            const int ex = inc - sub;
            if (ex < k && k <= inc) {           // exactly one lane
                int cum = ex;
                #pragma unroll
                for (int i = 0; i < 8; ++i) {
                    const int h = hist[lid * 8 + i];
                    if (k <= cum + h) {
                        s_prefix = prefix | ((unsigned)(lid * 8 + i) << shift);
                        s_k = k - cum;
                        break;
                    }
                    cum += h;
                }
            }
        }
    }
    __syncthreads();

    const float thr = __uint_as_float(s_prefix);   // exact kth-smallest p
    if (active) out[b * NP + t] = (p > thr) ? 1.0f : 0.0f;
}

// ---------------------------------------------------------------------------
// Launch contract: colsum, then finalize as a PDL secondary so its ramp
// overlaps colsum's tail.
// ---------------------------------------------------------------------------
extern "C" void kernel_launch(void* const* d_in, const int* in_sizes, int n_in,
                              void* d_out, int out_size) {
    const float* att   = (const float*)d_in[0];   // [12,4,12,785,785] f32
    const float* gamma = (const float*)d_in[1];   // [784] f32
    const float* beta  = (const float*)d_in[2];   // [784] f32
    float* out = (float*)d_out;                   // [4,784] f32

    colsum_vec<<<NSLAB * CHUNKS, NTHR>>>(att);

    cudaLaunchConfig_t cfg = {};
    cfg.gridDim  = dim3(NB);
    cfg.blockDim = dim3(1024);
    cfg.dynamicSmemBytes = 0;
    cfg.stream = 0;                               // legacy default stream
    cudaLaunchAttribute attr[1];
    attr[0].id = cudaLaunchAttributeProgrammaticStreamSerialization;
    attr[0].val.programmaticStreamSerializationAllowed = 1;
    cfg.attrs = attr;
    cfg.numAttrs = 1;
    cudaLaunchKernelEx(&cfg, finalize_kernel, gamma, beta, out);
}